// round 11
// baseline (speedup 1.0000x reference)
#include <cuda_runtime.h>

#define NN 100000
#define NE 3200000
#define NG 4096
#define NRL 5
#define NK (NN*NRL)   // 500000 segments
#define HID 32

// ---------------- scratch (static device globals; no allocation) ----------------
__device__ int   g_cnt[NK];      // zero-initialized; re-zeroed by k_scanC each run
__device__ int   g_off[NK];
__device__ float g_inv[NK];
__device__ int   g_pack[NE];     // key<<12 | rank-within-segment
__device__ int   g_ssrc[NE];
__device__ int   g_bsum[512];
__device__ int   g_bsumex[512];
__device__ float g_h[(long)NN*128];

// ---------------- build counts + per-edge rank ----------------
__global__ void k_build(const int* __restrict__ ei, const int* __restrict__ et) {
    int e = blockIdx.x * blockDim.x + threadIdx.x;
    if (e >= NE) return;
    int d = ei[NE + e];
    int t = et[e];
    int key = d * NRL + t;
    int r = atomicAdd(&g_cnt[key], 1);
    g_pack[e] = (key << 12) | r;
}

// ---------------- 3-kernel scan (proven) ----------------
__global__ void k_scanA() {
    __shared__ int sh[1024];
    int i = blockIdx.x * 1024 + threadIdx.x;
    int v = (i < NK) ? g_cnt[i] : 0;
    sh[threadIdx.x] = v;
    __syncthreads();
    for (int o = 1; o < 1024; o <<= 1) {
        int t = (threadIdx.x >= o) ? sh[threadIdx.x - o] : 0;
        __syncthreads();
        sh[threadIdx.x] += t;
        __syncthreads();
    }
    if (i < NK) g_off[i] = sh[threadIdx.x] - v;   // exclusive within block
    if (threadIdx.x == 1023) g_bsum[blockIdx.x] = sh[1023];
}

__global__ void k_scanB(int nb) {
    __shared__ int sh[512];
    int v = (threadIdx.x < nb) ? g_bsum[threadIdx.x] : 0;
    sh[threadIdx.x] = v;
    __syncthreads();
    for (int o = 1; o < 512; o <<= 1) {
        int t = (threadIdx.x >= o) ? sh[threadIdx.x - o] : 0;
        __syncthreads();
        sh[threadIdx.x] += t;
        __syncthreads();
    }
    g_bsumex[threadIdx.x] = sh[threadIdx.x] - v;
}

__global__ void k_scanC() {
    int i = blockIdx.x * blockDim.x + threadIdx.x;
    if (i >= NK) return;
    int o = g_off[i] + g_bsumex[i >> 10];
    g_off[i] = o;
    int c = g_cnt[i];
    g_inv[i] = 1.0f / (float)(c > 0 ? c : 1);
    g_cnt[i] = 0;   // ready for next replay's k_build
}

// ---------------- scatter: position from pack (no second atomic) ----------------
__global__ void k_scatter(const int* __restrict__ ei) {
    int e = blockIdx.x * blockDim.x + threadIdx.x;
    if (e >= NE) return;
    int pack = g_pack[e];
    int key = pack >> 12;
    int rank = pack & 0xFFF;
    g_ssrc[g_off[key] + rank] = ei[e];
}

// ---------------- fused RGCN layer (IN_C = 32), node-pair transform ----------
// 8 warps x 8 nodes, lane = feature. Gather two nodes into Ash rows, then one
// transform loop shares each W read across both accumulators.
__device__ __forceinline__ void gather_node32(
    int n, const float* __restrict__ X, const float* __restrict__ csh,
    float* __restrict__ row, int lane)
{
    float a0 = 0.f, a1 = 0.f, a2 = 0.f, a3 = 0.f;
    int e0 = g_off[n * NRL];
    #pragma unroll
    for (int r = 0; r < NRL; r++) {
        int seg = n * NRL + r;
        int e1 = (seg == NK - 1) ? NE : g_off[seg + 1];
        float s0 = 0.f, s1 = 0.f, s2 = 0.f, s3 = 0.f;
        int e = e0;
        for (; e + 3 < e1; e += 4) {
            int ia = g_ssrc[e + 0];
            int ib = g_ssrc[e + 1];
            int ic = g_ssrc[e + 2];
            int id = g_ssrc[e + 3];
            s0 += X[ia * 128];
            s1 += X[ib * 128];
            s2 += X[ic * 128];
            s3 += X[id * 128];
        }
        for (; e < e1; e++) s0 += X[g_ssrc[e] * 128];
        e0 = e1;
        float iv = g_inv[seg] * ((s0 + s1) + (s2 + s3));
        a0 = fmaf(csh[r * 4 + 0], iv, a0);
        a1 = fmaf(csh[r * 4 + 1], iv, a1);
        a2 = fmaf(csh[r * 4 + 2], iv, a2);
        a3 = fmaf(csh[r * 4 + 3], iv, a3);
    }
    row[0 * 32 + lane] = a0;
    row[1 * 32 + lane] = a1;
    row[2 * 32 + lane] = a2;
    row[3 * 32 + lane] = a3;
    row[4 * 32 + lane] = X[n * 128];
}

__global__ void __launch_bounds__(256) k_layer32(
    int xoff,
    const float* __restrict__ basis, const float* __restrict__ comp,
    const float* __restrict__ root, const float* __restrict__ bias,
    int yoff)
{
    const int WPB = 8;   // warps per block
    const int NPW = 8;   // nodes per warp
    __shared__ float Wsh[160 * 32];
    __shared__ float csh[NRL * 4];
    __shared__ float bsh[32];
    __shared__ __align__(16) float Ash[WPB][2 * 160];

    int tid = threadIdx.x, w = tid >> 5, lane = tid & 31;
    for (int j = tid; j < 128 * 32; j += 256) Wsh[j] = basis[j];
    for (int j = tid; j < 32 * 32; j += 256) Wsh[128 * 32 + j] = root[j];
    if (tid < NRL * 4) csh[tid] = comp[tid];
    if (tid < 32) bsh[tid] = bias[tid];
    __syncthreads();

    const float* __restrict__ X = g_h + xoff + lane;   // per-lane feature column

    int nbase = (blockIdx.x * WPB + w) * NPW;
    for (int ni = 0; ni < NPW; ni += 2) {
        int n0 = nbase + ni;
        int n1 = n0 + 1;
        if (n0 >= NN) break;   // uniform across warp
        gather_node32(n0, X, csh, &Ash[w][0], lane);
        if (n1 < NN) gather_node32(n1, X, csh, &Ash[w][160], lane);
        __syncwarp();

        float bb = bsh[lane];
        float acc0 = bb, acc1 = bb;
        const float4* A0 = (const float4*)&Ash[w][0];
        const float4* A1 = (const float4*)&Ash[w][160];
        #pragma unroll 8
        for (int jv = 0; jv < 40; jv++) {
            float4 u0 = A0[jv];
            float4 u1 = A1[jv];
            const float* wp = &Wsh[jv * 128 + lane];
            float w0 = wp[0], w1 = wp[32], w2 = wp[64], w3 = wp[96];
            acc0 = fmaf(u0.x, w0, acc0); acc1 = fmaf(u1.x, w0, acc1);
            acc0 = fmaf(u0.y, w1, acc0); acc1 = fmaf(u1.y, w1, acc1);
            acc0 = fmaf(u0.z, w2, acc0); acc1 = fmaf(u1.z, w2, acc1);
            acc0 = fmaf(u0.w, w3, acc0); acc1 = fmaf(u1.w, w3, acc1);
        }
        g_h[(long)n0 * 128 + yoff + lane] = tanhf(acc0);
        if (n1 < NN) g_h[(long)n1 * 128 + yoff + lane] = tanhf(acc1);
        __syncwarp();
    }
}

// ---------------- layer 0 (IN_C = 4): 8 edges x 4 features across the warp -----
__global__ void __launch_bounds__(256) k_layer0(
    const float* __restrict__ x,
    const float* __restrict__ basis, const float* __restrict__ comp,
    const float* __restrict__ root, const float* __restrict__ bias)
{
    const int IN_C = 4;
    const int WPB = 8;
    const int NPW = 8;
    __shared__ float Wsh[5 * IN_C * 32];
    __shared__ float csh[NRL * 4];
    __shared__ float bsh[32];
    __shared__ float Ash[WPB][5 * IN_C];

    int tid = threadIdx.x, w = tid >> 5, lane = tid & 31;
    for (int j = tid; j < 4 * IN_C * 32; j += 256) Wsh[j] = basis[j];
    if (tid < IN_C * 32) Wsh[4 * IN_C * 32 + tid] = root[tid];
    if (tid < NRL * 4) csh[tid] = comp[tid];
    if (tid < 32) bsh[tid] = bias[tid];
    __syncthreads();

    int sub  = lane >> 2;   // 0..7 edge subgroup
    int feat = lane & 3;    // 0..3 feature

    int nbase = (blockIdx.x * WPB + w) * NPW;
    for (int ni = 0; ni < NPW; ni++) {
        int n = nbase + ni;
        if (n >= NN) break;   // uniform across warp
        float a0 = 0.f, a1 = 0.f, a2 = 0.f, a3 = 0.f;
        int e0 = g_off[n * NRL];
        #pragma unroll
        for (int r = 0; r < NRL; r++) {
            int seg = n * NRL + r;
            int e1 = (seg == NK - 1) ? NE : g_off[seg + 1];
            float sum = 0.f;
            for (int e = e0 + sub; e < e1; e += 8) {
                int s = g_ssrc[e];
                sum += x[s * 4 + feat];
            }
            e0 = e1;
            sum += __shfl_down_sync(0xffffffffu, sum, 16);
            sum += __shfl_down_sync(0xffffffffu, sum, 8);
            sum += __shfl_down_sync(0xffffffffu, sum, 4);
            if (lane < 4) {
                float iv = g_inv[seg] * sum;
                a0 = fmaf(csh[r * 4 + 0], iv, a0);
                a1 = fmaf(csh[r * 4 + 1], iv, a1);
                a2 = fmaf(csh[r * 4 + 2], iv, a2);
                a3 = fmaf(csh[r * 4 + 3], iv, a3);
            }
        }
        if (lane < 4) {
            Ash[w][0 * IN_C + lane] = a0;
            Ash[w][1 * IN_C + lane] = a1;
            Ash[w][2 * IN_C + lane] = a2;
            Ash[w][3 * IN_C + lane] = a3;
            Ash[w][4 * IN_C + lane] = x[n * 4 + lane];
        }
        __syncwarp();
        float acc = bsh[lane];
        #pragma unroll
        for (int j = 0; j < 5 * IN_C; j++)
            acc = fmaf(Ash[w][j], Wsh[j * 32 + lane], acc);
        g_h[(long)n * 128 + lane] = tanhf(acc);
        __syncwarp();
    }
}

// ---------------- MLP readout ----------------
__global__ void __launch_bounds__(128) k_mlp(
    const int* __restrict__ uidx, const int* __restrict__ iidx,
    const float* __restrict__ w1, const float* __restrict__ b1,
    const float* __restrict__ w2, const float* __restrict__ b2,
    float* __restrict__ out)
{
    const int GPB = 8;
    __shared__ float gsh[GPB * 256];
    __shared__ float red[128];
    int tid = threadIdx.x;
    int gbase = blockIdx.x * GPB;

    for (int idx = tid; idx < GPB * 256; idx += 128) {
        int gi = idx >> 8, k = idx & 255;
        int g = gbase + gi;
        int n = (k < 128) ? uidx[g] : iidx[g];
        gsh[idx] = g_h[(long)n * 128 + (k & 127)];
    }
    __syncthreads();

    float acc[GPB];
    float bb = b1[tid];
    #pragma unroll
    for (int gi = 0; gi < GPB; gi++) acc[gi] = bb;

    for (int k = 0; k < 256; k++) {
        float wv = w1[k * 128 + tid];
        #pragma unroll
        for (int gi = 0; gi < GPB; gi++)
            acc[gi] = fmaf(gsh[gi * 256 + k], wv, acc[gi]);
    }

    float w2v = w2[tid];
    float b2v = b2[0];
    #pragma unroll
    for (int gi = 0; gi < GPB; gi++) {
        float z = fmaxf(acc[gi], 0.f) * w2v;
        red[tid] = z;
        __syncthreads();
        for (int o = 64; o > 0; o >>= 1) {
            if (tid < o) red[tid] += red[tid + o];
            __syncthreads();
        }
        if (tid == 0) out[gbase + gi] = red[0] + b2v;
        __syncthreads();
    }
}

// ---------------- launcher ----------------
extern "C" void kernel_launch(void* const* d_in, const int* in_sizes, int n_in,
                              void* d_out, int out_size)
{
    const float* x  = (const float*)d_in[0];
    const int*   ei = (const int*)d_in[1];
    const int*   et = (const int*)d_in[2];
    const int*   ui = (const int*)d_in[3];
    const int*   ii = (const int*)d_in[4];
    const float* basis[4] = {(const float*)d_in[5],  (const float*)d_in[9],
                             (const float*)d_in[13], (const float*)d_in[17]};
    const float* comp[4]  = {(const float*)d_in[6],  (const float*)d_in[10],
                             (const float*)d_in[14], (const float*)d_in[18]};
    const float* root[4]  = {(const float*)d_in[7],  (const float*)d_in[11],
                             (const float*)d_in[15], (const float*)d_in[19]};
    const float* bias[4]  = {(const float*)d_in[8],  (const float*)d_in[12],
                             (const float*)d_in[16], (const float*)d_in[20]};
    const float* w1 = (const float*)d_in[21];
    const float* b1 = (const float*)d_in[22];
    const float* w2 = (const float*)d_in[23];
    const float* b2 = (const float*)d_in[24];
    float* out = (float*)d_out;

    // counting sort by (dst, rel): build gives each edge its rank via the
    // atomicAdd return; scatter computes final position without a second atomic.
    k_build<<<(NE + 255) / 256, 256>>>(ei, et);
    k_scanA<<<(NK + 1023) / 1024, 1024>>>();
    k_scanB<<<1, 512>>>((NK + 1023) / 1024);
    k_scanC<<<(NK + 255) / 256, 256>>>();
    k_scatter<<<(NE + 255) / 256, 256>>>(ei);

    // layer 0: input x [N,4]
    k_layer0<<<(NN + 63) / 64, 256>>>(x, basis[0], comp[0], root[0], bias[0]);

    // layers 1..3: 64 nodes/block (8 warps x 8 nodes, node pairs)
    int lblocks = (NN + 63) / 64;
    k_layer32<<<lblocks, 256>>>(0,  basis[1], comp[1], root[1], bias[1], 32);
    k_layer32<<<lblocks, 256>>>(32, basis[2], comp[2], root[2], bias[2], 64);
    k_layer32<<<lblocks, 256>>>(64, basis[3], comp[3], root[3], bias[3], 96);

    // MLP readout
    k_mlp<<<NG / 8, 128>>>(ui, ii, w1, b1, w2, b2, out);
}

// round 13
// speedup vs baseline: 1.1482x; 1.1482x over previous
#include <cuda_runtime.h>

#define NN 100000
#define NE 3200000
#define NG 4096
#define NRL 5
#define NK (NN*NRL)   // 500000 segments
#define HID 32
#define WT_STRIDE 164   // padded row stride for transposed W (4-way conflict, optimal)

// ---------------- scratch (static device globals; no allocation) ----------------
__device__ int   g_cnt[NK];      // zero-initialized; re-zeroed by k_scanC each run
__device__ int   g_off[NK];
__device__ int   g_cur[NK];
__device__ float g_inv[NK];
__device__ int   g_ssrc[NE];
__device__ int   g_bsum[512];
__device__ int   g_bsumex[512];
__device__ float g_h[(long)NN*128];

// ---------------- build counts ----------------
__global__ void k_build(const int* __restrict__ ei, const int* __restrict__ et) {
    int e = blockIdx.x * blockDim.x + threadIdx.x;
    if (e >= NE) return;
    int d = ei[NE + e];
    int t = et[e];
    atomicAdd(&g_cnt[d * NRL + t], 1);
}

// ---------------- 3-kernel scan (proven) ----------------
__global__ void k_scanA() {
    __shared__ int sh[1024];
    int i = blockIdx.x * 1024 + threadIdx.x;
    int v = (i < NK) ? g_cnt[i] : 0;
    sh[threadIdx.x] = v;
    __syncthreads();
    for (int o = 1; o < 1024; o <<= 1) {
        int t = (threadIdx.x >= o) ? sh[threadIdx.x - o] : 0;
        __syncthreads();
        sh[threadIdx.x] += t;
        __syncthreads();
    }
    if (i < NK) g_off[i] = sh[threadIdx.x] - v;   // exclusive within block
    if (threadIdx.x == 1023) g_bsum[blockIdx.x] = sh[1023];
}

__global__ void k_scanB(int nb) {
    __shared__ int sh[512];
    int v = (threadIdx.x < nb) ? g_bsum[threadIdx.x] : 0;
    sh[threadIdx.x] = v;
    __syncthreads();
    for (int o = 1; o < 512; o <<= 1) {
        int t = (threadIdx.x >= o) ? sh[threadIdx.x - o] : 0;
        __syncthreads();
        sh[threadIdx.x] += t;
        __syncthreads();
    }
    g_bsumex[threadIdx.x] = sh[threadIdx.x] - v;
}

__global__ void k_scanC() {
    int i = blockIdx.x * blockDim.x + threadIdx.x;
    if (i >= NK) return;
    int o = g_off[i] + g_bsumex[i >> 10];
    g_off[i] = o;
    g_cur[i] = o;
    int c = g_cnt[i];
    g_inv[i] = 1.0f / (float)(c > 0 ? c : 1);
    g_cnt[i] = 0;   // ready for next replay's k_build
}

// ---------------- scatter (counting-sort pass 2) ----------------
__global__ void k_scatter(const int* __restrict__ ei, const int* __restrict__ et) {
    int e = blockIdx.x * blockDim.x + threadIdx.x;
    if (e >= NE) return;
    int s = ei[e];
    int d = ei[NE + e];
    int t = et[e];
    int k = d * NRL + t;
    int p = atomicAdd(&g_cur[k], 1);
    g_ssrc[p] = s;
}

// ---------------- fused RGCN layer (IN_C = 32) ----------------
// 8 warps x 8 nodes, lane = feature/output. Per node: unrolled edge gather
// with 4 independent accumulators, then 160-row transform where BOTH sides
// are float4: A via broadcast LDS.128, W via per-lane LDS.128 from the
// transposed Wt[out][row] layout (row stride 164 -> 4-way conflict, optimal).
__global__ void __launch_bounds__(256) k_layer32(
    int xoff,
    const float* __restrict__ basis, const float* __restrict__ comp,
    const float* __restrict__ root, const float* __restrict__ bias,
    int yoff)
{
    const int IN_C = 32;
    const int WPB = 8;   // warps per block
    const int NPW = 8;   // nodes per warp
    __shared__ __align__(16) float WTsh[32 * WT_STRIDE];   // transposed: [out][row]
    __shared__ float csh[NRL * 4];
    __shared__ float bsh[32];
    __shared__ __align__(16) float Ash[WPB][5 * IN_C];

    int tid = threadIdx.x, w = tid >> 5, lane = tid & 31;
    // transpose basis (rows 0..127) and root (rows 128..159) into WTsh
    for (int idx = tid; idx < 128 * 32; idx += 256) {
        int row = idx >> 5, o = idx & 31;
        WTsh[o * WT_STRIDE + row] = basis[idx];
    }
    for (int idx = tid; idx < 32 * 32; idx += 256) {
        int row = idx >> 5, o = idx & 31;
        WTsh[o * WT_STRIDE + 128 + row] = root[idx];
    }
    if (tid < NRL * 4) csh[tid] = comp[tid];
    if (tid < 32) bsh[tid] = bias[tid];
    __syncthreads();

    const float* __restrict__ X = g_h + xoff + lane;   // per-lane feature column
    const float4* __restrict__ Wv = (const float4*)&WTsh[lane * WT_STRIDE];

    int nbase = (blockIdx.x * WPB + w) * NPW;
    for (int ni = 0; ni < NPW; ni++) {
        int n = nbase + ni;
        if (n >= NN) break;   // uniform across warp
        float a0 = 0.f, a1 = 0.f, a2 = 0.f, a3 = 0.f;
        int e0 = g_off[n * NRL];
        #pragma unroll
        for (int r = 0; r < NRL; r++) {
            int seg = n * NRL + r;
            int e1 = (seg == NK - 1) ? NE : g_off[seg + 1];
            float s0 = 0.f, s1 = 0.f, s2 = 0.f, s3 = 0.f;
            int e = e0;
            for (; e + 3 < e1; e += 4) {
                int ia = g_ssrc[e + 0];
                int ib = g_ssrc[e + 1];
                int ic = g_ssrc[e + 2];
                int id = g_ssrc[e + 3];
                s0 += X[ia * 128];
                s1 += X[ib * 128];
                s2 += X[ic * 128];
                s3 += X[id * 128];
            }
            for (; e < e1; e++) s0 += X[g_ssrc[e] * 128];
            e0 = e1;
            float iv = g_inv[seg] * ((s0 + s1) + (s2 + s3));
            a0 = fmaf(csh[r * 4 + 0], iv, a0);
            a1 = fmaf(csh[r * 4 + 1], iv, a1);
            a2 = fmaf(csh[r * 4 + 2], iv, a2);
            a3 = fmaf(csh[r * 4 + 3], iv, a3);
        }
        Ash[w][0 * IN_C + lane] = a0;
        Ash[w][1 * IN_C + lane] = a1;
        Ash[w][2 * IN_C + lane] = a2;
        Ash[w][3 * IN_C + lane] = a3;
        Ash[w][4 * IN_C + lane] = X[n * 128];
        __syncwarp();
        // transform: both sides float4 (A broadcast, W per-lane column)
        float acc = bsh[lane];
        const float4* Av = (const float4*)&Ash[w][0];   // 40 float4s
        #pragma unroll 8
        for (int jv = 0; jv < 40; jv++) {
            float4 a4 = Av[jv];
            float4 w4 = Wv[jv];
            acc = fmaf(a4.x, w4.x, acc);
            acc = fmaf(a4.y, w4.y, acc);
            acc = fmaf(a4.z, w4.z, acc);
            acc = fmaf(a4.w, w4.w, acc);
        }
        g_h[(long)n * 128 + yoff + lane] = tanhf(acc);
        __syncwarp();
    }
}

// ---------------- layer 0 (IN_C = 4): 8 edges x 4 features across the warp -----
__global__ void __launch_bounds__(256) k_layer0(
    const float* __restrict__ x,
    const float* __restrict__ basis, const float* __restrict__ comp,
    const float* __restrict__ root, const float* __restrict__ bias)
{
    const int IN_C = 4;
    const int WPB = 8;
    const int NPW = 8;
    __shared__ float Wsh[5 * IN_C * 32];
    __shared__ float csh[NRL * 4];
    __shared__ float bsh[32];
    __shared__ float Ash[WPB][5 * IN_C];

    int tid = threadIdx.x, w = tid >> 5, lane = tid & 31;
    for (int j = tid; j < 4 * IN_C * 32; j += 256) Wsh[j] = basis[j];
    if (tid < IN_C * 32) Wsh[4 * IN_C * 32 + tid] = root[tid];
    if (tid < NRL * 4) csh[tid] = comp[tid];
    if (tid < 32) bsh[tid] = bias[tid];
    __syncthreads();

    int sub  = lane >> 2;   // 0..7 edge subgroup
    int feat = lane & 3;    // 0..3 feature

    int nbase = (blockIdx.x * WPB + w) * NPW;
    for (int ni = 0; ni < NPW; ni++) {
        int n = nbase + ni;
        if (n >= NN) break;   // uniform across warp
        float a0 = 0.f, a1 = 0.f, a2 = 0.f, a3 = 0.f;
        int e0 = g_off[n * NRL];
        #pragma unroll
        for (int r = 0; r < NRL; r++) {
            int seg = n * NRL + r;
            int e1 = (seg == NK - 1) ? NE : g_off[seg + 1];
            float sum = 0.f;
            for (int e = e0 + sub; e < e1; e += 8) {
                int s = g_ssrc[e];
                sum += x[s * 4 + feat];
            }
            e0 = e1;
            sum += __shfl_down_sync(0xffffffffu, sum, 16);
            sum += __shfl_down_sync(0xffffffffu, sum, 8);
            sum += __shfl_down_sync(0xffffffffu, sum, 4);
            if (lane < 4) {
                float iv = g_inv[seg] * sum;
                a0 = fmaf(csh[r * 4 + 0], iv, a0);
                a1 = fmaf(csh[r * 4 + 1], iv, a1);
                a2 = fmaf(csh[r * 4 + 2], iv, a2);
                a3 = fmaf(csh[r * 4 + 3], iv, a3);
            }
        }
        if (lane < 4) {
            Ash[w][0 * IN_C + lane] = a0;
            Ash[w][1 * IN_C + lane] = a1;
            Ash[w][2 * IN_C + lane] = a2;
            Ash[w][3 * IN_C + lane] = a3;
            Ash[w][4 * IN_C + lane] = x[n * 4 + lane];
        }
        __syncwarp();
        float acc = bsh[lane];
        #pragma unroll
        for (int j = 0; j < 5 * IN_C; j++)
            acc = fmaf(Ash[w][j], Wsh[j * 32 + lane], acc);
        g_h[(long)n * 128 + lane] = tanhf(acc);
        __syncwarp();
    }
}

// ---------------- MLP readout ----------------
__global__ void __launch_bounds__(128) k_mlp(
    const int* __restrict__ uidx, const int* __restrict__ iidx,
    const float* __restrict__ w1, const float* __restrict__ b1,
    const float* __restrict__ w2, const float* __restrict__ b2,
    float* __restrict__ out)
{
    const int GPB = 8;
    __shared__ float gsh[GPB * 256];
    __shared__ float red[128];
    int tid = threadIdx.x;
    int gbase = blockIdx.x * GPB;

    for (int idx = tid; idx < GPB * 256; idx += 128) {
        int gi = idx >> 8, k = idx & 255;
        int g = gbase + gi;
        int n = (k < 128) ? uidx[g] : iidx[g];
        gsh[idx] = g_h[(long)n * 128 + (k & 127)];
    }
    __syncthreads();

    float acc[GPB];
    float bb = b1[tid];
    #pragma unroll
    for (int gi = 0; gi < GPB; gi++) acc[gi] = bb;

    for (int k = 0; k < 256; k++) {
        float wv = w1[k * 128 + tid];
        #pragma unroll
        for (int gi = 0; gi < GPB; gi++)
            acc[gi] = fmaf(gsh[gi * 256 + k], wv, acc[gi]);
    }

    float w2v = w2[tid];
    float b2v = b2[0];
    #pragma unroll
    for (int gi = 0; gi < GPB; gi++) {
        float z = fmaxf(acc[gi], 0.f) * w2v;
        red[tid] = z;
        __syncthreads();
        for (int o = 64; o > 0; o >>= 1) {
            if (tid < o) red[tid] += red[tid + o];
            __syncthreads();
        }
        if (tid == 0) out[gbase + gi] = red[0] + b2v;
        __syncthreads();
    }
}

// ---------------- launcher ----------------
extern "C" void kernel_launch(void* const* d_in, const int* in_sizes, int n_in,
                              void* d_out, int out_size)
{
    const float* x  = (const float*)d_in[0];
    const int*   ei = (const int*)d_in[1];
    const int*   et = (const int*)d_in[2];
    const int*   ui = (const int*)d_in[3];
    const int*   ii = (const int*)d_in[4];
    const float* basis[4] = {(const float*)d_in[5],  (const float*)d_in[9],
                             (const float*)d_in[13], (const float*)d_in[17]};
    const float* comp[4]  = {(const float*)d_in[6],  (const float*)d_in[10],
                             (const float*)d_in[14], (const float*)d_in[18]};
    const float* root[4]  = {(const float*)d_in[7],  (const float*)d_in[11],
                             (const float*)d_in[15], (const float*)d_in[19]};
    const float* bias[4]  = {(const float*)d_in[8],  (const float*)d_in[12],
                             (const float*)d_in[16], (const float*)d_in[20]};
    const float* w1 = (const float*)d_in[21];
    const float* b1 = (const float*)d_in[22];
    const float* w2 = (const float*)d_in[23];
    const float* b2 = (const float*)d_in[24];
    float* out = (float*)d_out;

    // counting sort by (dst, rel): g_cnt starts zero (static init on run 1,
    // re-zeroed by k_scanC for subsequent graph replays)
    k_build<<<(NE + 255) / 256, 256>>>(ei, et);
    k_scanA<<<(NK + 1023) / 1024, 1024>>>();
    k_scanB<<<1, 512>>>((NK + 1023) / 1024);
    k_scanC<<<(NK + 255) / 256, 256>>>();
    k_scatter<<<(NE + 255) / 256, 256>>>(ei, et);

    // layer 0: input x [N,4]
    k_layer0<<<(NN + 63) / 64, 256>>>(x, basis[0], comp[0], root[0], bias[0]);

    // layers 1..3: 64 nodes/block (8 warps x 8 nodes)
    int lblocks = (NN + 63) / 64;
    k_layer32<<<lblocks, 256>>>(0,  basis[1], comp[1], root[1], bias[1], 32);
    k_layer32<<<lblocks, 256>>>(32, basis[2], comp[2], root[2], bias[2], 64);
    k_layer32<<<lblocks, 256>>>(64, basis[3], comp[3], root[3], bias[3], 96);

    // MLP readout
    k_mlp<<<NG / 8, 128>>>(ui, ii, w1, b1, w2, b2, out);
}

// round 14
// speedup vs baseline: 1.1833x; 1.0306x over previous
#include <cuda_runtime.h>

#define NN 100000
#define NE 3200000
#define NG 4096
#define NRL 5
#define NK (NN*NRL)   // 500000 segments
#define HID 32

// fast hardware tanh (sm_75+): single MUFU-class instruction
__device__ __forceinline__ float htanh(float v) {
    float r;
    asm("tanh.approx.f32 %0, %1;" : "=f"(r) : "f"(v));
    return r;
}

// ---------------- scratch (static device globals; no allocation) ----------------
__device__ int   g_cnt[NK];      // zero-initialized; re-zeroed by k_scanC each run
__device__ int   g_off[NK];
__device__ int   g_cur[NK];
__device__ float g_inv[NK];
__device__ int   g_ssrc[NE];
__device__ int   g_bsum[512];
__device__ int   g_bsumex[512];
__device__ float g_h[(long)NN*128];

// ---------------- build counts ----------------
__global__ void k_build(const int* __restrict__ ei, const int* __restrict__ et) {
    int e = blockIdx.x * blockDim.x + threadIdx.x;
    if (e >= NE) return;
    int d = ei[NE + e];
    int t = et[e];
    atomicAdd(&g_cnt[d * NRL + t], 1);
}

// ---------------- 3-kernel scan (proven) ----------------
__global__ void k_scanA() {
    __shared__ int sh[1024];
    int i = blockIdx.x * 1024 + threadIdx.x;
    int v = (i < NK) ? g_cnt[i] : 0;
    sh[threadIdx.x] = v;
    __syncthreads();
    for (int o = 1; o < 1024; o <<= 1) {
        int t = (threadIdx.x >= o) ? sh[threadIdx.x - o] : 0;
        __syncthreads();
        sh[threadIdx.x] += t;
        __syncthreads();
    }
    if (i < NK) g_off[i] = sh[threadIdx.x] - v;   // exclusive within block
    if (threadIdx.x == 1023) g_bsum[blockIdx.x] = sh[1023];
}

__global__ void k_scanB(int nb) {
    __shared__ int sh[512];
    int v = (threadIdx.x < nb) ? g_bsum[threadIdx.x] : 0;
    sh[threadIdx.x] = v;
    __syncthreads();
    for (int o = 1; o < 512; o <<= 1) {
        int t = (threadIdx.x >= o) ? sh[threadIdx.x - o] : 0;
        __syncthreads();
        sh[threadIdx.x] += t;
        __syncthreads();
    }
    g_bsumex[threadIdx.x] = sh[threadIdx.x] - v;
}

__global__ void k_scanC() {
    int i = blockIdx.x * blockDim.x + threadIdx.x;
    if (i >= NK) return;
    int o = g_off[i] + g_bsumex[i >> 10];
    g_off[i] = o;
    g_cur[i] = o;
    int c = g_cnt[i];
    g_inv[i] = 1.0f / (float)(c > 0 ? c : 1);
    g_cnt[i] = 0;   // ready for next replay's k_build
}

// ---------------- scatter (counting-sort pass 2) ----------------
__global__ void k_scatter(const int* __restrict__ ei, const int* __restrict__ et) {
    int e = blockIdx.x * blockDim.x + threadIdx.x;
    if (e >= NE) return;
    int s = ei[e];
    int d = ei[NE + e];
    int t = et[e];
    int k = d * NRL + t;
    int p = atomicAdd(&g_cur[k], 1);
    g_ssrc[p] = s;
}

// ---------------- fused RGCN layer (IN_C = 32) ----------------
// 8 warps x 8 nodes, lane = feature. Per node: unrolled edge gather with 4
// independent accumulators (high MLP), then 160-row transform with A read
// as broadcast LDS.128 (4 rows per load) and W as scalar LDS.
__global__ void __launch_bounds__(256) k_layer32(
    int xoff,
    const float* __restrict__ basis, const float* __restrict__ comp,
    const float* __restrict__ root, const float* __restrict__ bias,
    int yoff)
{
    const int IN_C = 32;
    const int WPB = 8;   // warps per block
    const int NPW = 8;   // nodes per warp
    __shared__ float Wsh[5 * IN_C * 32];
    __shared__ float csh[NRL * 4];
    __shared__ float bsh[32];
    __shared__ __align__(16) float Ash[WPB][5 * IN_C];

    int tid = threadIdx.x, w = tid >> 5, lane = tid & 31;
    for (int j = tid; j < 4 * IN_C * 32; j += 256) Wsh[j] = basis[j];
    for (int j = tid; j < IN_C * 32; j += 256) Wsh[4 * IN_C * 32 + j] = root[j];
    if (tid < NRL * 4) csh[tid] = comp[tid];
    if (tid < 32) bsh[tid] = bias[tid];
    __syncthreads();

    const float* __restrict__ X = g_h + xoff + lane;   // per-lane feature column

    int nbase = (blockIdx.x * WPB + w) * NPW;
    for (int ni = 0; ni < NPW; ni++) {
        int n = nbase + ni;
        if (n >= NN) break;   // uniform across warp
        float a0 = 0.f, a1 = 0.f, a2 = 0.f, a3 = 0.f;
        int e0 = g_off[n * NRL];
        #pragma unroll
        for (int r = 0; r < NRL; r++) {
            int seg = n * NRL + r;
            int e1 = (seg == NK - 1) ? NE : g_off[seg + 1];
            float s0 = 0.f, s1 = 0.f, s2 = 0.f, s3 = 0.f;
            int e = e0;
            for (; e + 3 < e1; e += 4) {
                int ia = g_ssrc[e + 0];
                int ib = g_ssrc[e + 1];
                int ic = g_ssrc[e + 2];
                int id = g_ssrc[e + 3];
                s0 += X[ia * 128];
                s1 += X[ib * 128];
                s2 += X[ic * 128];
                s3 += X[id * 128];
            }
            for (; e < e1; e++) s0 += X[g_ssrc[e] * 128];
            e0 = e1;
            float iv = g_inv[seg] * ((s0 + s1) + (s2 + s3));
            a0 = fmaf(csh[r * 4 + 0], iv, a0);
            a1 = fmaf(csh[r * 4 + 1], iv, a1);
            a2 = fmaf(csh[r * 4 + 2], iv, a2);
            a3 = fmaf(csh[r * 4 + 3], iv, a3);
        }
        Ash[w][0 * IN_C + lane] = a0;
        Ash[w][1 * IN_C + lane] = a1;
        Ash[w][2 * IN_C + lane] = a2;
        Ash[w][3 * IN_C + lane] = a3;
        Ash[w][4 * IN_C + lane] = X[n * 128];
        __syncwarp();
        // transform: A via broadcast LDS.128 (4 rows/load), W scalar LDS
        float acc = bsh[lane];
        const float4* Av = (const float4*)&Ash[w][0];   // 40 float4s
        #pragma unroll 8
        for (int jv = 0; jv < 40; jv++) {
            float4 a4 = Av[jv];
            const float* wp = &Wsh[jv * 128 + lane];
            acc = fmaf(a4.x, wp[0],  acc);
            acc = fmaf(a4.y, wp[32], acc);
            acc = fmaf(a4.z, wp[64], acc);
            acc = fmaf(a4.w, wp[96], acc);
        }
        g_h[(long)n * 128 + yoff + lane] = htanh(acc);
        __syncwarp();
    }
}

// ---------------- layer 0 (IN_C = 4): 8 edges x 4 features across the warp -----
__global__ void __launch_bounds__(256) k_layer0(
    const float* __restrict__ x,
    const float* __restrict__ basis, const float* __restrict__ comp,
    const float* __restrict__ root, const float* __restrict__ bias)
{
    const int IN_C = 4;
    const int WPB = 8;
    const int NPW = 8;
    __shared__ float Wsh[5 * IN_C * 32];
    __shared__ float csh[NRL * 4];
    __shared__ float bsh[32];
    __shared__ float Ash[WPB][5 * IN_C];

    int tid = threadIdx.x, w = tid >> 5, lane = tid & 31;
    for (int j = tid; j < 4 * IN_C * 32; j += 256) Wsh[j] = basis[j];
    if (tid < IN_C * 32) Wsh[4 * IN_C * 32 + tid] = root[tid];
    if (tid < NRL * 4) csh[tid] = comp[tid];
    if (tid < 32) bsh[tid] = bias[tid];
    __syncthreads();

    int sub  = lane >> 2;   // 0..7 edge subgroup
    int feat = lane & 3;    // 0..3 feature

    int nbase = (blockIdx.x * WPB + w) * NPW;
    for (int ni = 0; ni < NPW; ni++) {
        int n = nbase + ni;
        if (n >= NN) break;   // uniform across warp
        float a0 = 0.f, a1 = 0.f, a2 = 0.f, a3 = 0.f;
        int e0 = g_off[n * NRL];
        #pragma unroll
        for (int r = 0; r < NRL; r++) {
            int seg = n * NRL + r;
            int e1 = (seg == NK - 1) ? NE : g_off[seg + 1];
            float sum = 0.f;
            for (int e = e0 + sub; e < e1; e += 8) {
                int s = g_ssrc[e];
                sum += x[s * 4 + feat];
            }
            e0 = e1;
            sum += __shfl_down_sync(0xffffffffu, sum, 16);
            sum += __shfl_down_sync(0xffffffffu, sum, 8);
            sum += __shfl_down_sync(0xffffffffu, sum, 4);
            if (lane < 4) {
                float iv = g_inv[seg] * sum;
                a0 = fmaf(csh[r * 4 + 0], iv, a0);
                a1 = fmaf(csh[r * 4 + 1], iv, a1);
                a2 = fmaf(csh[r * 4 + 2], iv, a2);
                a3 = fmaf(csh[r * 4 + 3], iv, a3);
            }
        }
        if (lane < 4) {
            Ash[w][0 * IN_C + lane] = a0;
            Ash[w][1 * IN_C + lane] = a1;
            Ash[w][2 * IN_C + lane] = a2;
            Ash[w][3 * IN_C + lane] = a3;
            Ash[w][4 * IN_C + lane] = x[n * 4 + lane];
        }
        __syncwarp();
        float acc = bsh[lane];
        #pragma unroll
        for (int j = 0; j < 5 * IN_C; j++)
            acc = fmaf(Ash[w][j], Wsh[j * 32 + lane], acc);
        g_h[(long)n * 128 + lane] = htanh(acc);
        __syncwarp();
    }
}

// ---------------- MLP readout ----------------
__global__ void __launch_bounds__(128) k_mlp(
    const int* __restrict__ uidx, const int* __restrict__ iidx,
    const float* __restrict__ w1, const float* __restrict__ b1,
    const float* __restrict__ w2, const float* __restrict__ b2,
    float* __restrict__ out)
{
    const int GPB = 8;
    __shared__ float gsh[GPB * 256];
    __shared__ float red[128];
    int tid = threadIdx.x;
    int gbase = blockIdx.x * GPB;

    for (int idx = tid; idx < GPB * 256; idx += 128) {
        int gi = idx >> 8, k = idx & 255;
        int g = gbase + gi;
        int n = (k < 128) ? uidx[g] : iidx[g];
        gsh[idx] = g_h[(long)n * 128 + (k & 127)];
    }
    __syncthreads();

    float acc[GPB];
    float bb = b1[tid];
    #pragma unroll
    for (int gi = 0; gi < GPB; gi++) acc[gi] = bb;

    for (int k = 0; k < 256; k++) {
        float wv = w1[k * 128 + tid];
        #pragma unroll
        for (int gi = 0; gi < GPB; gi++)
            acc[gi] = fmaf(gsh[gi * 256 + k], wv, acc[gi]);
    }

    float w2v = w2[tid];
    float b2v = b2[0];
    #pragma unroll
    for (int gi = 0; gi < GPB; gi++) {
        float z = fmaxf(acc[gi], 0.f) * w2v;
        red[tid] = z;
        __syncthreads();
        for (int o = 64; o > 0; o >>= 1) {
            if (tid < o) red[tid] += red[tid + o];
            __syncthreads();
        }
        if (tid == 0) out[gbase + gi] = red[0] + b2v;
        __syncthreads();
    }
}

// ---------------- launcher ----------------
extern "C" void kernel_launch(void* const* d_in, const int* in_sizes, int n_in,
                              void* d_out, int out_size)
{
    const float* x  = (const float*)d_in[0];
    const int*   ei = (const int*)d_in[1];
    const int*   et = (const int*)d_in[2];
    const int*   ui = (const int*)d_in[3];
    const int*   ii = (const int*)d_in[4];
    const float* basis[4] = {(const float*)d_in[5],  (const float*)d_in[9],
                             (const float*)d_in[13], (const float*)d_in[17]};
    const float* comp[4]  = {(const float*)d_in[6],  (const float*)d_in[10],
                             (const float*)d_in[14], (const float*)d_in[18]};
    const float* root[4]  = {(const float*)d_in[7],  (const float*)d_in[11],
                             (const float*)d_in[15], (const float*)d_in[19]};
    const float* bias[4]  = {(const float*)d_in[8],  (const float*)d_in[12],
                             (const float*)d_in[16], (const float*)d_in[20]};
    const float* w1 = (const float*)d_in[21];
    const float* b1 = (const float*)d_in[22];
    const float* w2 = (const float*)d_in[23];
    const float* b2 = (const float*)d_in[24];
    float* out = (float*)d_out;

    // counting sort by (dst, rel): g_cnt starts zero (static init on run 1,
    // re-zeroed by k_scanC for subsequent graph replays)
    k_build<<<(NE + 255) / 256, 256>>>(ei, et);
    k_scanA<<<(NK + 1023) / 1024, 1024>>>();
    k_scanB<<<1, 512>>>((NK + 1023) / 1024);
    k_scanC<<<(NK + 255) / 256, 256>>>();
    k_scatter<<<(NE + 255) / 256, 256>>>(ei, et);

    // layer 0: input x [N,4]
    k_layer0<<<(NN + 63) / 64, 256>>>(x, basis[0], comp[0], root[0], bias[0]);

    // layers 1..3: 64 nodes/block (8 warps x 8 nodes)
    int lblocks = (NN + 63) / 64;
    k_layer32<<<lblocks, 256>>>(0,  basis[1], comp[1], root[1], bias[1], 32);
    k_layer32<<<lblocks, 256>>>(32, basis[2], comp[2], root[2], bias[2], 64);
    k_layer32<<<lblocks, 256>>>(64, basis[3], comp[3], root[3], bias[3], 96);

    // MLP readout
    k_mlp<<<NG / 8, 128>>>(ui, ii, w1, b1, w2, b2, out);
}